// round 7
// baseline (speedup 1.0000x reference)
#include <cuda_runtime.h>
#include <cuda_fp16.h>
#include <stdint.h>

// MultiLevelSparseHashEncoding — round 7.
// R6 showed occupancy doesn't help: dual floor (issue ~89K cyc/SM, LDS ~96K).
// This round lowers the ISSUE floor:
//  * 8 corner weights precomputed as 4 half2 regs; inner loop is
//    LOP3 -> LDS -> HFMA2 with weight broadcast via half-lane SELECTOR
//    (__low2half2/__high2half2 fold into HFMA2 .H0_H0/.H1_H1, zero instr).
//  * coordinate math fused to 3 FFMA (continuity makes boundary rounding safe).

#define NLVL 16
#define NENC 16384
#define NPTS (1 << 20)
#define TPB  512
#define PPB  8192
#define GPT  (PPB / TPB)            // 16 points per thread
#define SMEM_BYTES ((NENC + 1) * (int)sizeof(__half2))   // 65540
#define SCALE    4096.0f
#define INV_SCALE (1.0f / 4096.0f)

__constant__ int c_res[NLVL] = {16, 20, 25, 32, 40, 50, 64, 80,
                                101, 128, 161, 203, 256, 322, 406, 512};
__constant__ int c_nle[NLVL] = {4096, 8000, 15625, 16384, 16384, 16384,
                                16384, 16384, 16384, 16384, 16384, 16384,
                                16384, 16384, 16384, 16384};

__device__ float    g_xs[3u * NPTS];                 // SoA coords (12 MB)
__device__ unsigned g_stage[(size_t)NLVL * NPTS];    // [level][point] half2 bits

// ---------------------------------------------------------------- pre-kernel
__global__ __launch_bounds__(1024)
void transpose_x_kernel(const float* __restrict__ x)
{
    const int p = blockIdx.x * 1024 + threadIdx.x;
    const float a = x[3 * p + 0];
    const float b = x[3 * p + 1];
    const float c = x[3 * p + 2];
    g_xs[p]             = a;
    g_xs[NPTS + p]      = b;
    g_xs[2u * NPTS + p] = c;
}

// ---------------------------------------------------------------- per-level
// returns fp16 accumulator bits, still scaled by 2^12
template <bool DIRECT>
__device__ __forceinline__ unsigned
level_feat(const __half2* __restrict__ tab, const int R,
           const float xv0, const float xv1, const float xv2)
{
    const float halfR = 0.5f * (float)R;
    const float cadd  = halfR - 0.5f;
    const float t0 = fmaf(xv0, halfR, cadd);
    const float t1 = fmaf(xv1, halfR, cadd);
    const float t2 = fmaf(xv2, halfR, cadd);

    const float fl0 = floorf(t0), fl1 = floorf(t1), fl2 = floorf(t2);
    const float fr0 = t0 - fl0, fr1 = t1 - fl1, fr2 = t2 - fl2;
    const int   i0  = (int)fl0, i1 = (int)fl1, i2 = (int)fl2;

    // per-dim weights with validity folded in (invalid corner -> 0)
    const float wx0 = i0     >= 0 ? 1.0f - fr0 : 0.0f;
    const float wx1 = i0 + 1 <  R ? fr0        : 0.0f;
    const float wy0 = i1     >= 0 ? 1.0f - fr1 : 0.0f;
    const float wy1 = i1 + 1 <  R ? fr1        : 0.0f;
    const float wz0 = i2     >= 0 ? 1.0f - fr2 : 0.0f;
    const float wz1 = i2 + 1 <  R ? fr2        : 0.0f;

    // 8 corner weights packed as 4 half2: w[ox][oy] = (..*wz0, ..*wz1)
    const __half2 wz2 = __floats2half2_rn(wz0, wz1);
    const __half2 xyA = __floats2half2_rn(wx0 * wy0, wx0 * wy1);
    const __half2 xyB = __floats2half2_rn(wx1 * wy0, wx1 * wy1);
    const __half2 w00 = __hmul2(__low2half2 (xyA), wz2);
    const __half2 w01 = __hmul2(__high2half2(xyA), wz2);
    const __half2 w10 = __hmul2(__low2half2 (xyB), wz2);
    const __half2 w11 = __hmul2(__high2half2(xyB), wz2);

    unsigned kx[2], kyz[4];
    if (DIRECT) {
        const int R2 = R * R;
        const int a0 = max(i0, 0), a1 = min(i0 + 1, R - 1);
        const int b0 = max(i1, 0), b1 = min(i1 + 1, R - 1);
        const int d0 = max(i2, 0), d1 = min(i2 + 1, R - 1);
        kx[0] = (unsigned)(a0 * R2); kx[1] = (unsigned)(a1 * R2);
        kyz[0] = (unsigned)(b0 * R + d0); kyz[1] = (unsigned)(b0 * R + d1);
        kyz[2] = (unsigned)(b1 * R + d0); kyz[3] = (unsigned)(b1 * R + d1);
    } else {
        kx[0] = (unsigned)i0; kx[1] = (unsigned)(i0 + 1);
        const unsigned hy0 = (unsigned)i1 * 2654435761u;
        const unsigned hy1 = hy0 + 2654435761u;
        const unsigned hz0 = (unsigned)i2 * 805459861u;
        const unsigned hz1 = hz0 + 805459861u;
        kyz[0] = hy0 ^ hz0; kyz[1] = hy0 ^ hz1;
        kyz[2] = hy1 ^ hz0; kyz[3] = hy1 ^ hz1;
    }
    const unsigned mask = NENC - 1;
    const __half2 wsel[4] = {w00, w01, w10, w11};

    __half2 acc = __float2half2_rn(0.0f);
    #pragma unroll
    for (int c = 0; c < 8; ++c) {
        const int ox = (c >> 2) & 1, oyz = c & 3;
        unsigned id;
        if (DIRECT) id = kx[ox] + kyz[oyz];
        else        id = (kx[ox] ^ kyz[oyz]) & mask;        // one LOP3
        const __half2 wp = wsel[2 * ox + (oyz >> 1)];
        const __half2 w2 = (oyz & 1) ? __high2half2(wp)     // HFMA2 selector
                                     : __low2half2(wp);
        acc = __hfma2(w2, tab[id], acc);
    }
    return *reinterpret_cast<const unsigned*>(&acc);
}

// ---------------------------------------------------------------- main
__global__ __launch_bounds__(TPB, 3)
void hashgrid_level_kernel(const float* __restrict__ emb)
{
    extern __shared__ __half2 tab[];

    const int l     = blockIdx.x & (NLVL - 1);    // level = fastest grid dim
    const int chunk = blockIdx.x >> 4;
    const int R  = c_res[l];
    const int ne = c_nle[l];

    const float2* __restrict__ src =
        reinterpret_cast<const float2*>(emb) + (size_t)l * (NENC + 1);
    for (int i = threadIdx.x; i <= ne; i += TPB) {
        const float2 v = src[i];
        tab[i] = __floats2half2_rn(v.x * SCALE, v.y * SCALE);
    }
    __syncthreads();

    unsigned* __restrict__ stage = g_stage + (size_t)l * NPTS;

    int p = chunk * PPB + threadIdx.x;
    #pragma unroll 1
    for (int g = 0; g < GPT; ++g, p += TPB) {
        const float xv0 = g_xs[p];
        const float xv1 = g_xs[NPTS + p];
        const float xv2 = g_xs[2u * NPTS + p];

        unsigned r;
        if (l < 3) r = level_feat<true >(tab, R, xv0, xv1, xv2);
        else       r = level_feat<false>(tab, R, xv0, xv1, xv2);

        stage[p] = r;                              // coalesced 4 B store
    }
}

// ---------------------------------------------------------------- transpose
#define TPB3 256
__global__ __launch_bounds__(TPB3)
void transpose_out_kernel(float4* __restrict__ out)
{
    __shared__ unsigned arr[NLVL][TPB3 + 1];

    const int base = blockIdx.x * TPB3;
    const int tid  = threadIdx.x;

    #pragma unroll
    for (int m = 0; m < NLVL; ++m)
        arr[m][tid] = g_stage[(size_t)m * NPTS + base + tid];
    __syncthreads();

    #pragma unroll
    for (int k = 0; k < 8; ++k) {
        const int local = k * TPB3 + tid;         // float4 index within block
        const int p_off = local >> 3;
        const int j     = local & 7;              // level pair
        const unsigned a = arr[2 * j][p_off];
        const unsigned b = arr[2 * j + 1][p_off];
        const float2 fa = __half22float2(*reinterpret_cast<const __half2*>(&a));
        const float2 fb = __half22float2(*reinterpret_cast<const __half2*>(&b));
        out[(size_t)base * 8 + local] =
            make_float4(fa.x * INV_SCALE, fa.y * INV_SCALE,
                        fb.x * INV_SCALE, fb.y * INV_SCALE);
    }
}

// ---------------------------------------------------------------- launch
extern "C" void kernel_launch(void* const* d_in, const int* in_sizes, int n_in,
                              void* d_out, int out_size)
{
    (void)n_in; (void)out_size;
    const float* x;
    const float* emb;
    if (in_sizes[0] == 3 * NPTS) { x = (const float*)d_in[0]; emb = (const float*)d_in[1]; }
    else                         { x = (const float*)d_in[1]; emb = (const float*)d_in[0]; }
    float4* out = (float4*)d_out;

    cudaFuncSetAttribute(hashgrid_level_kernel,
                         cudaFuncAttributeMaxDynamicSharedMemorySize, SMEM_BYTES);

    transpose_x_kernel<<<NPTS / 1024, 1024>>>(x);

    const int blocks = (NPTS / PPB) * NLVL;       // 2048
    hashgrid_level_kernel<<<blocks, TPB, SMEM_BYTES>>>(emb);

    transpose_out_kernel<<<NPTS / TPB3, TPB3>>>(out);
}

// round 8
// speedup vs baseline: 1.6594x; 1.6594x over previous
#include <cuda_runtime.h>
#include <cuda_fp16.h>
#include <stdint.h>

// MultiLevelSparseHashEncoding — round 8.
// R7 FAILED (reg spills from half2 weight packing under tight launch bounds).
// Revert to the R5 pair-kernel body (best measured), add only:
//  * PERSISTENT 2-wave grid: 296 blocks = 8 pairs x 37 slices (exactly
//    2 waves of 148 SMs at 1 CTA/SM).  Tables staged ONCE per block and
//    amortized over 28340 points (was: re-staged by all 1024 blocks,
//    ~35K cyc/SM of pure staging overhead -> ~10K).
//  * fused-FFMA coordinate math (validated in R7, rel_err 5.9e-4).
//  * precombined y^z hash keys: hashed corner id = single LOP3.

#define NLVL 16
#define NENC 16384
#define NPTS (1 << 20)
#define TPB  1024
#define NPAIR 8
#define NSLICE 37
#define SLICE ((NPTS + NSLICE - 1) / NSLICE)       // 28340
#define SMEM_BYTES ((2 * (NENC + 1)) * (int)sizeof(__half2))   // 131080
#define SCALE    4096.0f
#define INV_SCALE (1.0f / 4096.0f)

__constant__ int c_res[NLVL] = {16, 20, 25, 32, 40, 50, 64, 80,
                                101, 128, 161, 203, 256, 322, 406, 512};
__constant__ int c_nle[NLVL] = {4096, 8000, 15625, 16384, 16384, 16384,
                                16384, 16384, 16384, 16384, 16384, 16384,
                                16384, 16384, 16384, 16384};

__device__ float g_xs[3u * NPTS];                  // SoA coords (12 MB)
__device__ uint2 g_stage[(size_t)NPAIR * NPTS];    // [pair][point] half4 bits

// ---------------------------------------------------------------- pre-kernel
__global__ __launch_bounds__(1024)
void transpose_x_kernel(const float* __restrict__ x)
{
    const int p = blockIdx.x * 1024 + threadIdx.x;
    const float a = x[3 * p + 0];
    const float b = x[3 * p + 1];
    const float c = x[3 * p + 2];
    g_xs[p]             = a;
    g_xs[NPTS + p]      = b;
    g_xs[2u * NPTS + p] = c;
}

// ---------------------------------------------------------------- per-level
// returns the fp16 accumulator still scaled by 2^12
template <bool DIRECT>
__device__ __forceinline__ __half2
level_feat(const __half2* __restrict__ tab, const int R,
           const float xv0, const float xv1, const float xv2)
{
    const float halfR = 0.5f * (float)R;
    const float cadd  = halfR - 0.5f;
    const float t0 = fmaf(xv0, halfR, cadd);
    const float t1 = fmaf(xv1, halfR, cadd);
    const float t2 = fmaf(xv2, halfR, cadd);

    const float fl0 = floorf(t0), fl1 = floorf(t1), fl2 = floorf(t2);
    const float fr0 = t0 - fl0, fr1 = t1 - fl1, fr2 = t2 - fl2;
    const int   i0  = (int)fl0, i1 = (int)fl1, i2 = (int)fl2;

    // validity folded into per-dim weights: invalid corner -> weight 0
    const float wx0 = i0     >= 0 ? 1.0f - fr0 : 0.0f;
    const float wx1 = i0 + 1 <  R ? fr0        : 0.0f;
    const float wy0 = i1     >= 0 ? 1.0f - fr1 : 0.0f;
    const float wy1 = i1 + 1 <  R ? fr1        : 0.0f;
    const float wz[2] = {i2     >= 0 ? 1.0f - fr2 : 0.0f,
                         i2 + 1 <  R ? fr2        : 0.0f};
    const float wxy[4] = {wx0 * wy0, wx0 * wy1, wx1 * wy0, wx1 * wy1};

    unsigned kx[2], kyz[4];
    if (DIRECT) {
        const int R2 = R * R;
        const int a0 = max(i0, 0), a1 = min(i0 + 1, R - 1);
        const int b0 = max(i1, 0), b1 = min(i1 + 1, R - 1);
        const int d0 = max(i2, 0), d1 = min(i2 + 1, R - 1);
        kx[0] = (unsigned)(a0 * R2); kx[1] = (unsigned)(a1 * R2);
        kyz[0] = (unsigned)(b0 * R + d0); kyz[1] = (unsigned)(b0 * R + d1);
        kyz[2] = (unsigned)(b1 * R + d0); kyz[3] = (unsigned)(b1 * R + d1);
    } else {
        kx[0] = (unsigned)i0; kx[1] = (unsigned)(i0 + 1);
        const unsigned hy0 = (unsigned)i1 * 2654435761u;
        const unsigned hy1 = hy0 + 2654435761u;
        const unsigned hz0 = (unsigned)i2 * 805459861u;
        const unsigned hz1 = hz0 + 805459861u;
        kyz[0] = hy0 ^ hz0; kyz[1] = hy0 ^ hz1;
        kyz[2] = hy1 ^ hz0; kyz[3] = hy1 ^ hz1;
    }
    const unsigned mask = NENC - 1;

    __half2 acc = __float2half2_rn(0.0f);
    #pragma unroll
    for (int c = 0; c < 8; ++c) {
        const int ox = (c >> 2) & 1, oyz = c & 3;
        unsigned id;
        if (DIRECT) id = kx[ox] + kyz[oyz];
        else        id = (kx[ox] ^ kyz[oyz]) & mask;   // single LOP3
        const float   w  = wxy[2 * ox + (oyz >> 1)] * wz[oyz & 1];
        const __half2 w2 = __float2half2_rn(w);
        acc = __hfma2(w2, tab[id], acc);
    }
    return acc;
}

// ---------------------------------------------------------------- main
__global__ __launch_bounds__(TPB, 1)
void hashgrid_pair_kernel(const float* __restrict__ emb)
{
    extern __shared__ __half2 tab[];

    const int m     = blockIdx.x & (NPAIR - 1);   // pair index (fastest)
    const int slice = blockIdx.x >> 3;            // 0..NSLICE-1
    const int lA = 2 * m, lB = 2 * m + 1;
    const int RA = c_res[lA], RB = c_res[lB];
    const int neA = c_nle[lA], neB = c_nle[lB];

    __half2* tabA = tab;
    __half2* tabB = tab + (neA + 1);

    // stage both tables ONCE per block (persistent over ~28K points)
    const float2* __restrict__ srcA =
        reinterpret_cast<const float2*>(emb) + (size_t)lA * (NENC + 1);
    const float2* __restrict__ srcB =
        reinterpret_cast<const float2*>(emb) + (size_t)lB * (NENC + 1);
    for (int i = threadIdx.x; i <= neA; i += TPB) {
        const float2 v = srcA[i];
        tabA[i] = __floats2half2_rn(v.x * SCALE, v.y * SCALE);
    }
    for (int i = threadIdx.x; i <= neB; i += TPB) {
        const float2 v = srcB[i];
        tabB[i] = __floats2half2_rn(v.x * SCALE, v.y * SCALE);
    }
    __syncthreads();

    uint2* __restrict__ stage = g_stage + (size_t)m * NPTS;

    const int pend = min((slice + 1) * SLICE, NPTS);
    #pragma unroll 1
    for (int p = slice * SLICE + threadIdx.x; p < pend; p += TPB) {
        const float xv0 = g_xs[p];
        const float xv1 = g_xs[NPTS + p];
        const float xv2 = g_xs[2u * NPTS + p];

        __half2 rA, rB;
        if (lA < 3) rA = level_feat<true >(tabA, RA, xv0, xv1, xv2);
        else        rA = level_feat<false>(tabA, RA, xv0, xv1, xv2);
        if (lB < 3) rB = level_feat<true >(tabB, RB, xv0, xv1, xv2);
        else        rB = level_feat<false>(tabB, RB, xv0, xv1, xv2);

        stage[p] = make_uint2(*reinterpret_cast<unsigned*>(&rA),
                              *reinterpret_cast<unsigned*>(&rB));
    }
}

// ---------------------------------------------------------------- transpose
#define TPB3 256
__global__ __launch_bounds__(TPB3)
void transpose_out_kernel(float4* __restrict__ out)
{
    __shared__ uint2 arr[NPAIR][TPB3 + 1];        // pitch 257 -> conflict-free

    const int base = blockIdx.x * TPB3;
    const int tid  = threadIdx.x;

    #pragma unroll
    for (int m = 0; m < NPAIR; ++m)
        arr[m][tid] = g_stage[(size_t)m * NPTS + base + tid];
    __syncthreads();

    #pragma unroll
    for (int k = 0; k < 8; ++k) {
        const int local = k * TPB3 + tid;         // float4 index within block
        const int p_off = local >> 3;
        const int m     = local & 7;
        const uint2 v = arr[m][p_off];
        const float2 fa = __half22float2(*reinterpret_cast<const __half2*>(&v.x));
        const float2 fb = __half22float2(*reinterpret_cast<const __half2*>(&v.y));
        out[(size_t)base * 8 + local] =
            make_float4(fa.x * INV_SCALE, fa.y * INV_SCALE,
                        fb.x * INV_SCALE, fb.y * INV_SCALE);
    }
}

// ---------------------------------------------------------------- launch
extern "C" void kernel_launch(void* const* d_in, const int* in_sizes, int n_in,
                              void* d_out, int out_size)
{
    (void)n_in; (void)out_size;
    const float* x;
    const float* emb;
    if (in_sizes[0] == 3 * NPTS) { x = (const float*)d_in[0]; emb = (const float*)d_in[1]; }
    else                         { x = (const float*)d_in[1]; emb = (const float*)d_in[0]; }
    float4* out = (float4*)d_out;

    cudaFuncSetAttribute(hashgrid_pair_kernel,
                         cudaFuncAttributeMaxDynamicSharedMemorySize, SMEM_BYTES);

    transpose_x_kernel<<<NPTS / 1024, 1024>>>(x);

    const int blocks = NPAIR * NSLICE;            // 296 = exactly 2 waves
    hashgrid_pair_kernel<<<blocks, TPB, SMEM_BYTES>>>(emb);

    transpose_out_kernel<<<NPTS / TPB3, TPB3>>>(out);
}

// round 9
// speedup vs baseline: 1.7002x; 1.0246x over previous
#include <cuda_runtime.h>
#include <cuda_fp16.h>
#include <stdint.h>

// MultiLevelSparseHashEncoding — round 9.
// R8 WIN (104us) = persistent pair-blocks + amortized staging.  This round:
//  * main grid = 144 blocks = 8 pairs x 18 slices -> EXACTLY 1 wave at
//    1 CTA/SM: tables staged once total (was twice), no wave transition.
//  * x-transpose vectorized: 3x LDG.128 + 3x STG.128 per 4 points.
//  * out-transpose SMEM exchange transposed (arr[point][pair], pitch 9)
//    -> ~2-way instead of ~4-way bank conflicts on the read phase.
// Main-kernel body identical to R8 (rel_err 5.23e-4 validated).

#define NLVL 16
#define NENC 16384
#define NPTS (1 << 20)
#define TPB  1024
#define NPAIR 8
#define NSLICE 18
#define SLICE ((NPTS + NSLICE - 1) / NSLICE)       // 58255
#define SMEM_BYTES ((2 * (NENC + 1)) * (int)sizeof(__half2))   // 131080
#define SCALE    4096.0f
#define INV_SCALE (1.0f / 4096.0f)

__constant__ int c_res[NLVL] = {16, 20, 25, 32, 40, 50, 64, 80,
                                101, 128, 161, 203, 256, 322, 406, 512};
__constant__ int c_nle[NLVL] = {4096, 8000, 15625, 16384, 16384, 16384,
                                16384, 16384, 16384, 16384, 16384, 16384,
                                16384, 16384, 16384, 16384};

__device__ float g_xs[3u * NPTS];                  // SoA coords (12 MB)
__device__ uint2 g_stage[(size_t)NPAIR * NPTS];    // [pair][point] half4 bits

// ---------------------------------------------------------------- pre-kernel
// 4 points per thread: 3 float4 loads (12 floats) -> 3 float4 stores (planes)
__global__ __launch_bounds__(256)
void transpose_x_kernel(const float4* __restrict__ x4)
{
    const int i = blockIdx.x * 256 + threadIdx.x;      // float4-group index
    const float4 a = x4[3 * i + 0];                    // x0 y0 z0 x1
    const float4 b = x4[3 * i + 1];                    // y1 z1 x2 y2
    const float4 c = x4[3 * i + 2];                    // z2 x3 y3 z3
    float4* __restrict__ p0 = reinterpret_cast<float4*>(g_xs);
    float4* __restrict__ p1 = reinterpret_cast<float4*>(g_xs + NPTS);
    float4* __restrict__ p2 = reinterpret_cast<float4*>(g_xs + 2u * NPTS);
    p0[i] = make_float4(a.x, a.w, b.z, c.y);
    p1[i] = make_float4(a.y, b.x, b.w, c.z);
    p2[i] = make_float4(a.z, b.y, c.x, c.w);
}

// ---------------------------------------------------------------- per-level
// returns the fp16 accumulator still scaled by 2^12
template <bool DIRECT>
__device__ __forceinline__ __half2
level_feat(const __half2* __restrict__ tab, const int R,
           const float xv0, const float xv1, const float xv2)
{
    const float halfR = 0.5f * (float)R;
    const float cadd  = halfR - 0.5f;
    const float t0 = fmaf(xv0, halfR, cadd);
    const float t1 = fmaf(xv1, halfR, cadd);
    const float t2 = fmaf(xv2, halfR, cadd);

    const float fl0 = floorf(t0), fl1 = floorf(t1), fl2 = floorf(t2);
    const float fr0 = t0 - fl0, fr1 = t1 - fl1, fr2 = t2 - fl2;
    const int   i0  = (int)fl0, i1 = (int)fl1, i2 = (int)fl2;

    // validity folded into per-dim weights: invalid corner -> weight 0
    const float wx0 = i0     >= 0 ? 1.0f - fr0 : 0.0f;
    const float wx1 = i0 + 1 <  R ? fr0        : 0.0f;
    const float wy0 = i1     >= 0 ? 1.0f - fr1 : 0.0f;
    const float wy1 = i1 + 1 <  R ? fr1        : 0.0f;
    const float wz[2] = {i2     >= 0 ? 1.0f - fr2 : 0.0f,
                         i2 + 1 <  R ? fr2        : 0.0f};
    const float wxy[4] = {wx0 * wy0, wx0 * wy1, wx1 * wy0, wx1 * wy1};

    unsigned kx[2], kyz[4];
    if (DIRECT) {
        const int R2 = R * R;
        const int a0 = max(i0, 0), a1 = min(i0 + 1, R - 1);
        const int b0 = max(i1, 0), b1 = min(i1 + 1, R - 1);
        const int d0 = max(i2, 0), d1 = min(i2 + 1, R - 1);
        kx[0] = (unsigned)(a0 * R2); kx[1] = (unsigned)(a1 * R2);
        kyz[0] = (unsigned)(b0 * R + d0); kyz[1] = (unsigned)(b0 * R + d1);
        kyz[2] = (unsigned)(b1 * R + d0); kyz[3] = (unsigned)(b1 * R + d1);
    } else {
        kx[0] = (unsigned)i0; kx[1] = (unsigned)(i0 + 1);
        const unsigned hy0 = (unsigned)i1 * 2654435761u;
        const unsigned hy1 = hy0 + 2654435761u;
        const unsigned hz0 = (unsigned)i2 * 805459861u;
        const unsigned hz1 = hz0 + 805459861u;
        kyz[0] = hy0 ^ hz0; kyz[1] = hy0 ^ hz1;
        kyz[2] = hy1 ^ hz0; kyz[3] = hy1 ^ hz1;
    }
    const unsigned mask = NENC - 1;

    __half2 acc = __float2half2_rn(0.0f);
    #pragma unroll
    for (int c = 0; c < 8; ++c) {
        const int ox = (c >> 2) & 1, oyz = c & 3;
        unsigned id;
        if (DIRECT) id = kx[ox] + kyz[oyz];
        else        id = (kx[ox] ^ kyz[oyz]) & mask;   // single LOP3
        const float   w  = wxy[2 * ox + (oyz >> 1)] * wz[oyz & 1];
        const __half2 w2 = __float2half2_rn(w);
        acc = __hfma2(w2, tab[id], acc);
    }
    return acc;
}

// ---------------------------------------------------------------- main
__global__ __launch_bounds__(TPB, 1)
void hashgrid_pair_kernel(const float* __restrict__ emb)
{
    extern __shared__ __half2 tab[];

    const int m     = blockIdx.x & (NPAIR - 1);   // pair index (fastest)
    const int slice = blockIdx.x >> 3;            // 0..NSLICE-1
    const int lA = 2 * m, lB = 2 * m + 1;
    const int RA = c_res[lA], RB = c_res[lB];
    const int neA = c_nle[lA], neB = c_nle[lB];

    __half2* tabA = tab;
    __half2* tabB = tab + (neA + 1);

    // stage both tables ONCE (persistent over ~58K points)
    const float2* __restrict__ srcA =
        reinterpret_cast<const float2*>(emb) + (size_t)lA * (NENC + 1);
    const float2* __restrict__ srcB =
        reinterpret_cast<const float2*>(emb) + (size_t)lB * (NENC + 1);
    for (int i = threadIdx.x; i <= neA; i += TPB) {
        const float2 v = srcA[i];
        tabA[i] = __floats2half2_rn(v.x * SCALE, v.y * SCALE);
    }
    for (int i = threadIdx.x; i <= neB; i += TPB) {
        const float2 v = srcB[i];
        tabB[i] = __floats2half2_rn(v.x * SCALE, v.y * SCALE);
    }
    __syncthreads();

    uint2* __restrict__ stage = g_stage + (size_t)m * NPTS;

    const int pend = min((slice + 1) * SLICE, NPTS);
    #pragma unroll 1
    for (int p = slice * SLICE + threadIdx.x; p < pend; p += TPB) {
        const float xv0 = g_xs[p];
        const float xv1 = g_xs[NPTS + p];
        const float xv2 = g_xs[2u * NPTS + p];

        __half2 rA, rB;
        if (lA < 3) rA = level_feat<true >(tabA, RA, xv0, xv1, xv2);
        else        rA = level_feat<false>(tabA, RA, xv0, xv1, xv2);
        if (lB < 3) rB = level_feat<true >(tabB, RB, xv0, xv1, xv2);
        else        rB = level_feat<false>(tabB, RB, xv0, xv1, xv2);

        stage[p] = make_uint2(*reinterpret_cast<unsigned*>(&rA),
                              *reinterpret_cast<unsigned*>(&rB));
    }
}

// ---------------------------------------------------------------- transpose
#define TPB3 256
__global__ __launch_bounds__(TPB3)
void transpose_out_kernel(float4* __restrict__ out)
{
    __shared__ uint2 arr[TPB3][NPAIR + 1];        // [point][pair], pitch 9

    const int base = blockIdx.x * TPB3;
    const int tid  = threadIdx.x;

    #pragma unroll
    for (int m = 0; m < NPAIR; ++m)
        arr[tid][m] = g_stage[(size_t)m * NPTS + base + tid];
    __syncthreads();

    #pragma unroll
    for (int k = 0; k < 8; ++k) {
        const int local = k * TPB3 + tid;         // float4 index within block
        const int p_off = local >> 3;
        const int m     = local & 7;
        const uint2 v = arr[p_off][m];
        const float2 fa = __half22float2(*reinterpret_cast<const __half2*>(&v.x));
        const float2 fb = __half22float2(*reinterpret_cast<const __half2*>(&v.y));
        out[(size_t)base * 8 + local] =
            make_float4(fa.x * INV_SCALE, fa.y * INV_SCALE,
                        fb.x * INV_SCALE, fb.y * INV_SCALE);
    }
}

// ---------------------------------------------------------------- launch
extern "C" void kernel_launch(void* const* d_in, const int* in_sizes, int n_in,
                              void* d_out, int out_size)
{
    (void)n_in; (void)out_size;
    const float* x;
    const float* emb;
    if (in_sizes[0] == 3 * NPTS) { x = (const float*)d_in[0]; emb = (const float*)d_in[1]; }
    else                         { x = (const float*)d_in[1]; emb = (const float*)d_in[0]; }
    float4* out = (float4*)d_out;

    cudaFuncSetAttribute(hashgrid_pair_kernel,
                         cudaFuncAttributeMaxDynamicSharedMemorySize, SMEM_BYTES);

    transpose_x_kernel<<<NPTS / 4 / 256, 256>>>(
        reinterpret_cast<const float4*>(x));

    const int blocks = NPAIR * NSLICE;            // 144 = exactly 1 wave
    hashgrid_pair_kernel<<<blocks, TPB, SMEM_BYTES>>>(emb);

    transpose_out_kernel<<<NPTS / TPB3, TPB3>>>(out);
}